// round 6
// baseline (speedup 1.0000x reference)
#include <cuda_runtime.h>

// LSTM: T=512, B=4096, IN=1, H=12.
// One 16-lane segment per batch element; lane u (u<12) owns hidden unit u.
// All weights + state register-resident; h exchanged via warp shuffles.
// Matvecs use packed fp32x2 FMA (fma.rn.f32x2, sm_100+).

#define T_STEPS 512
#define BATCH   4096
#define HID     12

typedef unsigned long long ull;

__device__ __forceinline__ ull pack2(float lo, float hi) {
    ull r;
    asm("mov.b64 %0, {%1, %2};" : "=l"(r) : "f"(lo), "f"(hi));
    return r;
}
__device__ __forceinline__ void unpack2(ull v, float& lo, float& hi) {
    asm("mov.b64 {%0, %1}, %2;" : "=f"(lo), "=f"(hi) : "l"(v));
}
__device__ __forceinline__ ull fma2(ull a, ull b, ull c) {
    ull d;
    asm("fma.rn.f32x2 %0, %1, %2, %3;" : "=l"(d) : "l"(a), "l"(b), "l"(c));
    return d;
}

// sigmoid via fast exp (MUFU.EX2) + approx reciprocal: ~1e-6 rel err.
__device__ __forceinline__ float sigf(float x) {
    return __fdividef(1.0f, 1.0f + __expf(-x));
}
// tanh(x) = 1 - 2/(e^{2x}+1). Handles +/-inf saturation correctly.
__device__ __forceinline__ float tanh_fast(float x) {
    return 1.0f - __fdividef(2.0f, __expf(2.0f * x) + 1.0f);
}

__global__ void __launch_bounds__(128)
lstm_kernel(const float* __restrict__ X,
            const float* __restrict__ W_ih,
            const float* __restrict__ W_hh,
            const float* __restrict__ b_ih,
            const float* __restrict__ b_hh,
            const float* __restrict__ fc_w,
            const float* __restrict__ fc_b,
            float* __restrict__ Y)
{
    const int tid = threadIdx.x;
    const int ls  = tid & 15;                       // lane within 16-lane segment
    const int b   = blockIdx.x * 8 + (tid >> 4);    // batch element (512*8 = 4096)
    const int u   = (ls < 12) ? ls : 11;            // hidden unit (idle lanes clamp)

    // ---- Load per-unit weights into registers (once) ----
    // Gate order (PyTorch): i, f, g, o  -> W_hh rows g*12+u.
    ull   w2[4][6];     // W_hh rows packed as f32x2 pairs
    float wih[4], bias[4];
#pragma unroll
    for (int g = 0; g < 4; ++g) {
        const int row = g * HID + u;
#pragma unroll
        for (int k = 0; k < 6; ++k)
            w2[g][k] = pack2(W_hh[row * HID + 2 * k], W_hh[row * HID + 2 * k + 1]);
        wih[g]  = W_ih[row];               // IN == 1
        bias[g] = b_ih[row] + b_hh[row];
    }
    ull fc2[6];
#pragma unroll
    for (int k = 0; k < 6; ++k)
        fc2[k] = pack2(fc_w[2 * k], fc_w[2 * k + 1]);
    const ull fcb2 = pack2(fc_b[0], 0.0f);

    // ---- State ----
    ull h2[6];                                  // gathered h vector, packed
#pragma unroll
    for (int k = 0; k < 6; ++k) h2[k] = 0ULL;   // h0 = 0
    float c = 0.0f;

    const float* xp = X + b;
    float*       yp = Y + b;
    float x = xp[0];                            // x_0 (broadcast across segment lanes)

#pragma unroll 1
    for (int t = 0; t < T_STEPS; ++t) {
        // Prefetch next timestep's input (independent of recurrence).
        float xn = 0.0f;
        if (t + 1 < T_STEPS) xn = xp[BATCH];

        // ---- gates = x*W_ih + (b_ih+b_hh) + h @ W_hh^T, packed f32x2 dot ----
        float gate[4];
#pragma unroll
        for (int g = 0; g < 4; ++g) {
            ull acc = pack2(fmaf(x, wih[g], bias[g]), 0.0f);
#pragma unroll
            for (int k = 0; k < 6; ++k)
                acc = fma2(h2[k], w2[g][k], acc);
            float lo, hi; unpack2(acc, lo, hi);
            gate[g] = lo + hi;
        }

        const float ig = sigf(gate[0]);
        const float fg = sigf(gate[1]);
        const float gg = tanh_fast(gate[2]);
        const float og = sigf(gate[3]);

        c = fmaf(fg, c, ig * gg);
        const float h = og * tanh_fast(c);

        // ---- gather new h across the 12 active lanes of this segment ----
        float hj[12];
#pragma unroll
        for (int j = 0; j < 12; ++j)
            hj[j] = __shfl_sync(0xFFFFFFFFu, h, j, 16);
#pragma unroll
        for (int k = 0; k < 6; ++k)
            h2[k] = pack2(hj[2 * k], hj[2 * k + 1]);

        // ---- y_t = fc_w . h_t + fc_b (reuses gathered h; lane 0 stores) ----
        ull ya = fcb2;
#pragma unroll
        for (int k = 0; k < 6; ++k)
            ya = fma2(h2[k], fc2[k], ya);
        float ylo, yhi; unpack2(ya, ylo, yhi);
        if (ls == 0) *yp = ylo + yhi;

        yp += BATCH;
        xp += BATCH;
        x = xn;
    }
}

extern "C" void kernel_launch(void* const* d_in, const int* in_sizes, int n_in,
                              void* d_out, int out_size)
{
    const float* X    = (const float*)d_in[0];
    const float* W_ih = (const float*)d_in[1];
    const float* W_hh = (const float*)d_in[2];
    const float* b_ih = (const float*)d_in[3];
    const float* b_hh = (const float*)d_in[4];
    const float* fc_w = (const float*)d_in[5];
    const float* fc_b = (const float*)d_in[6];
    float* Y = (float*)d_out;

    // 4096 batches * 16 lanes = 65536 threads; 128 threads/block -> 512 blocks.
    lstm_kernel<<<512, 128>>>(X, W_ih, W_hh, b_ih, b_hh, fc_w, fc_b, Y);
}

// round 8
// speedup vs baseline: 1.0841x; 1.0841x over previous
#include <cuda_runtime.h>

// LSTM: T=512, B=4096, IN=1, H=12.
// One 16-lane segment per batch element; lane u (u<12) owns hidden unit u.
// All weights + state register-resident; h exchanged via warp shuffles.
// R6: __launch_bounds__(128,4) lifts the reg cap 96->128 (occupancy is
// grid-limited at ~4 CTAs/SM anyway) to kill local-memory spills of the
// weight arrays; fc layer turned into a 1-reg/lane butterfly reduction;
// gate dot chains split 2-way to shorten the dependency path.

#define T_STEPS 512
#define BATCH   4096
#define HID     12

typedef unsigned long long ull;

__device__ __forceinline__ ull pack2(float lo, float hi) {
    ull r;
    asm("mov.b64 %0, {%1, %2};" : "=l"(r) : "f"(lo), "f"(hi));
    return r;
}
__device__ __forceinline__ void unpack2(ull v, float& lo, float& hi) {
    asm("mov.b64 {%0, %1}, %2;" : "=f"(lo), "=f"(hi) : "l"(v));
}
__device__ __forceinline__ ull fma2(ull a, ull b, ull c) {
    ull d;
    asm("fma.rn.f32x2 %0, %1, %2, %3;" : "=l"(d) : "l"(a), "l"(b), "l"(c));
    return d;
}

// sigmoid via fast exp (MUFU.EX2) + approx reciprocal: ~1e-6 rel err.
__device__ __forceinline__ float sigf(float x) {
    return __fdividef(1.0f, 1.0f + __expf(-x));
}
// tanh(x) = 1 - 2/(e^{2x}+1). Handles +/-inf saturation correctly.
__device__ __forceinline__ float tanh_fast(float x) {
    return 1.0f - __fdividef(2.0f, __expf(2.0f * x) + 1.0f);
}

__global__ void __launch_bounds__(128, 4)
lstm_kernel(const float* __restrict__ X,
            const float* __restrict__ W_ih,
            const float* __restrict__ W_hh,
            const float* __restrict__ b_ih,
            const float* __restrict__ b_hh,
            const float* __restrict__ fc_w,
            const float* __restrict__ fc_b,
            float* __restrict__ Y)
{
    const int tid = threadIdx.x;
    const int ls  = tid & 15;                       // lane within 16-lane segment
    const int b   = blockIdx.x * 8 + (tid >> 4);    // batch element (512*8 = 4096)
    const int u   = (ls < 12) ? ls : 11;            // hidden unit (idle lanes clamp)

    // ---- Load per-unit weights into registers (once) ----
    // Gate order (PyTorch): i, f, g, o  -> W_hh rows g*12+u.
    ull   w2[4][6];     // W_hh rows packed as f32x2 pairs
    float wih[4], bias[4];
#pragma unroll
    for (int g = 0; g < 4; ++g) {
        const int row = g * HID + u;
#pragma unroll
        for (int k = 0; k < 6; ++k)
            w2[g][k] = pack2(W_hh[row * HID + 2 * k], W_hh[row * HID + 2 * k + 1]);
        wih[g]  = W_ih[row];               // IN == 1
        bias[g] = b_ih[row] + b_hh[row];
    }
    // fc weight: one register per lane (idle lanes contribute 0 to reduction).
    const float fcw = (ls < 12) ? fc_w[ls] : 0.0f;
    const float fcb = fc_b[0];

    // ---- State ----
    ull h2[6];                                  // gathered h vector, packed
#pragma unroll
    for (int k = 0; k < 6; ++k) h2[k] = 0ULL;   // h0 = 0
    float c = 0.0f;

    const float* xp = X + b;
    float*       yp = Y + b;
    float x = xp[0];                            // x_0 (broadcast across segment lanes)

#pragma unroll 1
    for (int t = 0; t < T_STEPS; ++t) {
        // Prefetch next timestep's input (independent of recurrence).
        float xn = 0.0f;
        if (t + 1 < T_STEPS) xn = xp[BATCH];

        // ---- gates = x*W_ih + (b_ih+b_hh) + h @ W_hh^T ----
        // Two parallel 3-deep packed-FMA chains per gate (shorter dep path).
        float gate[4];
#pragma unroll
        for (int g = 0; g < 4; ++g) {
            ull acc_a = pack2(fmaf(x, wih[g], bias[g]), 0.0f);
            ull acc_b = pack2(0.0f, 0.0f);
#pragma unroll
            for (int k = 0; k < 3; ++k) {
                acc_a = fma2(h2[k],     w2[g][k],     acc_a);
                acc_b = fma2(h2[k + 3], w2[g][k + 3], acc_b);
            }
            float la, ha, lb, hb;
            unpack2(acc_a, la, ha);
            unpack2(acc_b, lb, hb);
            gate[g] = (la + ha) + (lb + hb);
        }

        // c-path activations first (g, i, f), o off the critical path.
        const float gg = tanh_fast(gate[2]);
        const float ig = sigf(gate[0]);
        const float fg = sigf(gate[1]);
        const float og = sigf(gate[3]);

        c = fmaf(fg, c, ig * gg);
        const float h = og * tanh_fast(c);

        // ---- fc output: butterfly reduction over the 16-lane segment ----
        float r = fcw * h;                     // 0 on idle lanes
        r += __shfl_xor_sync(0xFFFFFFFFu, r, 8, 16);
        r += __shfl_xor_sync(0xFFFFFFFFu, r, 4, 16);
        r += __shfl_xor_sync(0xFFFFFFFFu, r, 2, 16);
        r += __shfl_xor_sync(0xFFFFFFFFu, r, 1, 16);
        if (ls == 0) *yp = r + fcb;

        // ---- gather new h across the 12 active lanes of this segment ----
        float hj[12];
#pragma unroll
        for (int j = 0; j < 12; ++j)
            hj[j] = __shfl_sync(0xFFFFFFFFu, h, j, 16);
#pragma unroll
        for (int k = 0; k < 6; ++k)
            h2[k] = pack2(hj[2 * k], hj[2 * k + 1]);

        yp += BATCH;
        xp += BATCH;
        x = xn;
    }
}

extern "C" void kernel_launch(void* const* d_in, const int* in_sizes, int n_in,
                              void* d_out, int out_size)
{
    const float* X    = (const float*)d_in[0];
    const float* W_ih = (const float*)d_in[1];
    const float* W_hh = (const float*)d_in[2];
    const float* b_ih = (const float*)d_in[3];
    const float* b_hh = (const float*)d_in[4];
    const float* fc_w = (const float*)d_in[5];
    const float* fc_b = (const float*)d_in[6];
    float* Y = (float*)d_out;

    // 4096 batches * 16 lanes = 65536 threads; 128 threads/block -> 512 blocks.
    lstm_kernel<<<512, 128>>>(X, W_ih, W_hh, b_ih, b_hh, fc_w, fc_b, Y);
}